// round 1
// baseline (speedup 1.0000x reference)
#include <cuda_runtime.h>
#include <stdint.h>

#define TT 32
#define NB 4
#define FRAMES (TT*NB)   // 128, frame index tn = t*NB + n

#define C0 128
#define H0 16
#define W0 16
#define C1 64
#define H1 31
#define W1 31
#define C2 32
#define H2 61
#define W2 61
#define C3 2
#define H3 121
#define W3 121

// ---- device scratch (no allocations allowed) ----
__device__ uint32_t g_mask0[FRAMES*H0*W0*(C0/32)];          // 131072 words
__device__ float    g_w1[9*C0*C1];                          // rearranged [kh][kw][ci][co], pre-scaled x2
__device__ float    g_z1[(size_t)FRAMES*H1*W1*C1];          // 7.87M floats
__device__ uint32_t g_mask1[FRAMES*H1*W1*(C1/32)];
__device__ float    g_w2[9*C1*C2];
__device__ float    g_z2[(size_t)FRAMES*H2*W2*C2];          // 15.2M floats
__device__ uint32_t g_mask2[FRAMES*H2*W2*(C2/32)];
__device__ float    g_w3[9*C2*C3];
__device__ float    g_z3[(size_t)FRAMES*H3*W3*C3];          // 3.75M floats
__device__ int      g_cnt[3];

// ---- pack input spikes into per-pixel channel bitmasks; zero counters ----
__global__ void k_mask0(const float* __restrict__ x) {
    int idx = blockIdx.x*blockDim.x + threadIdx.x;
    if (idx < 3) g_cnt[idx] = 0;
    const int total = FRAMES*H0*W0*(C0/32);
    if (idx >= total) return;
    int t    = idx & 31;
    int rest = idx >> 5;
    int pix  = rest % (H0*W0);  rest /= (H0*W0);
    int n    = rest % NB;
    int word = rest / NB;
    uint32_t m = 0;
    #pragma unroll
    for (int b = 0; b < 32; b++) {
        int ci = word*32 + b;
        float v = x[(((size_t)n*C0 + ci)*(H0*W0) + pix)*TT + t];  // consecutive t => coalesced
        if (v >= 0.5f) m |= (1u << b);
    }
    g_mask0[(((size_t)(t*NB+n))*(H0*W0) + pix)*(C0/32) + word] = m;
}

// ---- rearrange weights: wr[kh][kw][ci][co] = 2 * w[ci][co][kh][kw] ----
__global__ void k_wprep(const float* __restrict__ w, float* __restrict__ wr,
                        int cin, int cout) {
    int idx = blockIdx.x*blockDim.x + threadIdx.x;
    int total = cin*cout*9;
    if (idx >= total) return;
    int kw = idx % 3;
    int kh = (idx/3) % 3;
    int rest = idx/9;
    int co = rest % cout;
    int ci = rest / cout;
    wr[((kh*3+kw)*cin + ci)*cout + co] = 2.0f * w[((ci*cout + co)*3 + kh)*3 + kw];
}

// ---- sparse transposed conv (gather form, parity-specialized, weights in smem) ----
// MODE 0: even output rows (kh=1 only).  MODE 1: odd rows (kh=0,2).  MODE 2: all rows, all 9 taps in smem.
template<int CIN, int COUT, int HIN, int WIN, int MODE>
__global__ void __launch_bounds__(512)
k_conv(const uint32_t* __restrict__ maskIn, const float* __restrict__ wr,
       float* __restrict__ zOut) {
    constexpr int WORDS = CIN/32;
    constexpr int HOUT = 2*HIN-1, WOUT = 2*WIN-1;
    constexpr int NKH = (MODE==0) ? 1 : (MODE==1) ? 2 : 3;
    extern __shared__ float sW[];
    const int nw = NKH*3*CIN*COUT;
    for (int i = threadIdx.x; i < nw; i += blockDim.x) {
        int khi = i / (3*CIN*COUT);
        int rem = i - khi*(3*CIN*COUT);
        int kh  = (MODE==0) ? 1 : (MODE==1) ? (khi*2) : khi;
        sW[i] = wr[kh*(3*CIN*COUT) + rem];
    }
    __syncthreads();

    const int warp  = threadIdx.x >> 5;
    const int lane  = threadIdx.x & 31;
    const int nwarp = blockDim.x >> 5;
    constexpr int NROWS = (MODE==0) ? HIN : (MODE==1) ? (HIN-1) : HOUT;
    const int total = FRAMES*NROWS;

    for (int ri = blockIdx.x; ri < total; ri += gridDim.x) {
        const int tn = ri / NROWS;
        const int r  = ri - tn*NROWS;
        int oh, ih0, khi0, nkh;
        int ih1 = 0, khi1 = 0;
        if (MODE == 0)      { oh = 2*r;   ih0 = r;   khi0 = 0; nkh = 1; }
        else if (MODE == 1) { oh = 2*r+1; ih0 = r+1; khi0 = 0; ih1 = r; khi1 = 1; nkh = 2; }
        else {
            oh = r;
            if (oh & 1) { ih0 = (oh+1)>>1; khi0 = 0; ih1 = (oh-1)>>1; khi1 = 2; nkh = 2; }
            else        { ih0 = oh>>1;     khi0 = 1; nkh = 1; }
        }
        for (int ow = warp; ow < WOUT; ow += nwarp) {
            int kw0, iw0, nkw;
            int kw1 = 0, iw1 = 0;
            if (ow & 1) { kw0 = 0; iw0 = (ow+1)>>1; kw1 = 2; iw1 = (ow-1)>>1; nkw = 2; }
            else        { kw0 = 1; iw0 = ow>>1;     nkw = 1; }
            float acc0 = 0.f, acc1 = 0.f;
            for (int a = 0; a < nkh; a++) {
                const int khi = a ? khi1 : khi0;
                const int ih  = a ? ih1  : ih0;
                const uint32_t* mrow = maskIn + ((size_t)tn*HIN + ih)*WIN*WORDS;
                for (int b = 0; b < nkw; b++) {
                    const int kw = b ? kw1 : kw0;
                    const int iw = b ? iw1 : iw0;
                    uint32_t mv[WORDS];
                    if constexpr (WORDS == 4) {
                        uint4 u = *(const uint4*)(mrow + iw*4);
                        mv[0]=u.x; mv[1]=u.y; mv[2]=u.z; mv[3]=u.w;
                    } else if constexpr (WORDS == 2) {
                        uint2 u = *(const uint2*)(mrow + iw*2);
                        mv[0]=u.x; mv[1]=u.y;
                    } else {
                        mv[0] = mrow[iw];
                    }
                    const float* wb = sW + (khi*3 + kw)*(CIN*COUT);
                    #pragma unroll
                    for (int wo = 0; wo < WORDS; wo++) {
                        uint32_t m = mv[wo];
                        while (m) {
                            const int bit = __ffs(m) - 1;
                            m &= m - 1;
                            const int ci = wo*32 + bit;
                            if (COUT == 64) {
                                float2 v = *(const float2*)(wb + ci*COUT + (lane<<1));
                                acc0 += v.x; acc1 += v.y;
                            } else {
                                acc0 += wb[ci*COUT + lane];
                            }
                        }
                    }
                }
            }
            float* zp = zOut + (((size_t)tn*HOUT + oh)*WOUT + ow)*COUT;
            if (COUT == 64) *(float2*)(zp + (lane<<1)) = make_float2(acc0, acc1);
            else            zp[lane] = acc0;
        }
    }
}

// ---- block 3 conv: Cout=2, thread-per-output-pixel, all weights in smem ----
__global__ void k_conv3() {
    __shared__ float sW[9*C2*C3];
    for (int i = threadIdx.x; i < 9*C2*C3; i += blockDim.x) sW[i] = g_w3[i];
    __syncthreads();
    int idx = blockIdx.x*blockDim.x + threadIdx.x;
    const int total = FRAMES*H3*W3;
    if (idx >= total) return;
    int ow = idx % W3;
    int oh = (idx / W3) % H3;
    int tn = idx / (W3*H3);
    int kh0, ih0, nkh; int kh1 = 0, ih1 = 0;
    if (oh & 1) { kh0 = 0; ih0 = (oh+1)>>1; kh1 = 2; ih1 = (oh-1)>>1; nkh = 2; }
    else        { kh0 = 1; ih0 = oh>>1;     nkh = 1; }
    int kw0, iw0, nkw; int kw1 = 0, iw1 = 0;
    if (ow & 1) { kw0 = 0; iw0 = (ow+1)>>1; kw1 = 2; iw1 = (ow-1)>>1; nkw = 2; }
    else        { kw0 = 1; iw0 = ow>>1;     nkw = 1; }
    float acc0 = 0.f, acc1 = 0.f;
    for (int a = 0; a < nkh; a++) {
        const int kh = a ? kh1 : kh0;
        const int ih = a ? ih1 : ih0;
        for (int b = 0; b < nkw; b++) {
            const int kw = b ? kw1 : kw0;
            const int iw = b ? iw1 : iw0;
            uint32_t m = g_mask2[((size_t)tn*H2 + ih)*W2 + iw];
            const float* wb = sW + (kh*3 + kw)*(C2*C3);
            while (m) {
                const int bit = __ffs(m) - 1;
                m &= m - 1;
                float2 v = *(const float2*)(wb + bit*2);
                acc0 += v.x; acc1 += v.y;
            }
        }
    }
    *(float2*)(g_z3 + (size_t)idx*2) = make_float2(acc0, acc1);
}

// ---- CUBA LIF scan + spike bitmask packing + count ----
template<int C, int P, int LAYER>
__global__ void k_lif(const float* __restrict__ z, uint32_t* __restrict__ maskOut) {
    const int idx = blockIdx.x*blockDim.x + threadIdx.x;
    const int total = NB*P*C;   // multiple of 32 (C is 32 or 64)
    if (idx >= total) return;
    const int c   = idx % C;
    const int pix = (idx / C) % P;
    const int n   = idx / (C*P);
    const int lane = threadIdx.x & 31;
    const size_t base    = ((size_t)n*P + pix)*C + c;
    const size_t tstride = (size_t)NB*P*C;
    float cur = 0.f, vol = 0.f;
    int cnt = 0;
    #pragma unroll
    for (int t = 0; t < TT; t++) {
        float zv = z[(size_t)t*tstride + base];
        cur = 0.5f*cur + zv;
        vol = 0.5f*vol + cur;
        bool s = (vol >= 1.0f);
        vol = s ? 0.f : vol;
        cnt += s ? 1 : 0;
        uint32_t bal = __ballot_sync(0xffffffffu, s);
        if (lane == 0)
            maskOut[((size_t)(t*NB+n)*P + pix)*(C/32) + (c>>5)] = bal;
    }
    cnt = __reduce_add_sync(0xffffffffu, cnt);
    if (lane == 0) atomicAdd(&g_cnt[LAYER], cnt);
}

// ---- final LIF: writes output spikes in [N,C,H,W,T] layout + count ----
__global__ void k_lif3(float* __restrict__ out) {
    const int idx = blockIdx.x*blockDim.x + threadIdx.x;
    const int total = NB*H3*W3*C3;
    if (idx >= total) return;
    const int c   = idx % C3;
    const int pix = (idx / C3) % (H3*W3);
    const int n   = idx / (C3*H3*W3);
    const size_t base    = ((size_t)n*(H3*W3) + pix)*C3 + c;
    const size_t tstride = (size_t)NB*H3*W3*C3;
    float cur = 0.f, vol = 0.f;
    int cnt = 0;
    float res[TT];
    #pragma unroll
    for (int t = 0; t < TT; t++) {
        float zv = g_z3[(size_t)t*tstride + base];
        cur = 0.5f*cur + zv;
        vol = 0.5f*vol + cur;
        bool s = (vol >= 1.0f);
        vol = s ? 0.f : vol;
        res[t] = s ? 1.0f : 0.0f;
        cnt += s ? 1 : 0;
    }
    float4* op = (float4*)(out + (((size_t)n*C3 + c)*(H3*W3) + pix)*TT);
    #pragma unroll
    for (int q = 0; q < 8; q++)
        op[q] = make_float4(res[4*q], res[4*q+1], res[4*q+2], res[4*q+3]);
    atomicAdd(&g_cnt[2], cnt);
}

__global__ void k_final(float* out, int off) {
    if (threadIdx.x == 0) {
        out[off+0] = (float)g_cnt[0] * (1.0f / (float)((size_t)NB*C1*H1*W1*TT));
        out[off+1] = (float)g_cnt[1] * (1.0f / (float)((size_t)NB*C2*H2*W2*TT));
        out[off+2] = (float)g_cnt[2] * (1.0f / (float)((size_t)NB*C3*H3*W3*TT));
    }
}

extern "C" void kernel_launch(void* const* d_in, const int* in_sizes, int n_in,
                              void* d_out, int out_size) {
    const float* x  = (const float*)d_in[0];
    const float* w1 = (const float*)d_in[1];
    const float* w2 = (const float*)d_in[2];
    const float* w3 = (const float*)d_in[3];
    float* out = (float*)d_out;

    void *pm0, *pw1, *pz1, *pm1, *pw2, *pz2, *pm2, *pw3;
    cudaGetSymbolAddress(&pm0, g_mask0);
    cudaGetSymbolAddress(&pw1, g_w1);
    cudaGetSymbolAddress(&pz1, g_z1);
    cudaGetSymbolAddress(&pm1, g_mask1);
    cudaGetSymbolAddress(&pw2, g_w2);
    cudaGetSymbolAddress(&pz2, g_z2);
    cudaGetSymbolAddress(&pm2, g_mask2);
    cudaGetSymbolAddress(&pw3, g_w3);

    // opt-in to >48KB dynamic smem for the conv kernels
    cudaFuncSetAttribute((const void*)k_conv<C0,C1,H0,W0,0>,
                         cudaFuncAttributeMaxDynamicSharedMemorySize, 1*3*C0*C1*4);
    cudaFuncSetAttribute((const void*)k_conv<C0,C1,H0,W0,1>,
                         cudaFuncAttributeMaxDynamicSharedMemorySize, 2*3*C0*C1*4);
    cudaFuncSetAttribute((const void*)k_conv<C1,C2,H1,W1,2>,
                         cudaFuncAttributeMaxDynamicSharedMemorySize, 3*3*C1*C2*4);

    // stage 0: input bitmask pack (+ counter zero) and weight rearrange
    k_mask0<<<(FRAMES*H0*W0*(C0/32) + 255)/256, 256>>>(x);
    k_wprep<<<(C0*C1*9 + 255)/256, 256>>>(w1, (float*)pw1, C0, C1);
    k_wprep<<<(C1*C2*9 + 255)/256, 256>>>(w2, (float*)pw2, C1, C2);
    k_wprep<<<(C2*C3*9 + 255)/256, 256>>>(w3, (float*)pw3, C2, C3);

    // block 1: conv (even rows then odd rows) + LIF
    k_conv<C0,C1,H0,W0,0><<<296, 512, 1*3*C0*C1*4>>>((const uint32_t*)pm0, (const float*)pw1, (float*)pz1);
    k_conv<C0,C1,H0,W0,1><<<148, 512, 2*3*C0*C1*4>>>((const uint32_t*)pm0, (const float*)pw1, (float*)pz1);
    k_lif<C1, H1*W1, 0><<<(NB*H1*W1*C1)/256, 256>>>((const float*)pz1, (uint32_t*)pm1);

    // block 2: conv (all taps in smem) + LIF
    k_conv<C1,C2,H1,W1,2><<<444, 256, 3*3*C1*C2*4>>>((const uint32_t*)pm1, (const float*)pw2, (float*)pz2);
    k_lif<C2, H2*W2, 1><<<(NB*H2*W2*C2 + 255)/256, 256>>>((const float*)pz2, (uint32_t*)pm2);

    // block 3: conv + LIF (writes final output spikes)
    k_conv3<<<(FRAMES*H3*W3 + 255)/256, 256>>>();
    k_lif3<<<(NB*H3*W3*C3 + 255)/256, 256>>>(out);

    // means
    k_final<<<1, 32>>>(out, out_size - 3);
}